// round 1
// baseline (speedup 1.0000x reference)
#include <cuda_runtime.h>
#include <math.h>
#include <stdint.h>

#define NTOK 4096   // B*T
#define DD   1024   // model dim
#define NE   8      // experts
#define FF   4096   // ffn dim

// ---------------- device scratch (no allocations allowed) ----------------
__device__ int   g_cnt[NE];
__device__ int   g_list[NE * NTOK];
__device__ float g_wgt[NE * NTOK];
__device__ float g_H[(size_t)NE * NTOK * FF];   // 512 MB hidden scratch

// ---------------- init: zero output + counters every call ----------------
__global__ void init_kernel(float* out, float* counts) {
    size_t total = (size_t)NTOK * DD;
    for (size_t i = (size_t)blockIdx.x * blockDim.x + threadIdx.x; i < total;
         i += (size_t)gridDim.x * blockDim.x)
        out[i] = 0.f;
    if (blockIdx.x == 0 && threadIdx.x < NE) {
        g_cnt[threadIdx.x] = 0;
        if (counts) counts[threadIdx.x] = 0.f;
    }
}

// ---------------- gating: fp32 logits, stable top-2, routing ----------------
__global__ void gate_kernel(const float* __restrict__ x,
                            const float* __restrict__ gw,
                            const float* __restrict__ gb,
                            float* gate_logits, float* topk, float* counts) {
    __shared__ float xs[DD];
    __shared__ float lg[NE];
    int t = blockIdx.x;
    const float4* xr = (const float4*)(x + (size_t)t * DD);
    for (int i = threadIdx.x; i < DD / 4; i += blockDim.x)
        ((float4*)xs)[i] = xr[i];
    __syncthreads();

    int w = threadIdx.x >> 5, lane = threadIdx.x & 31;
    float s = 0.f;
    for (int j = lane; j < DD; j += 32) s += xs[j] * gw[j * NE + w];
#pragma unroll
    for (int o = 16; o; o >>= 1) s += __shfl_xor_sync(0xffffffffu, s, o);
    if (lane == 0) lg[w] = s + gb[w];
    __syncthreads();

    if (threadIdx.x == 0) {
        float v[NE];
#pragma unroll
        for (int e = 0; e < NE; e++) v[e] = lg[e];
        int i0 = 0;
        for (int e = 1; e < NE; e++) if (v[e] > v[i0]) i0 = e;   // stable argmax
        int i1 = -1;
        for (int e = 0; e < NE; e++) {
            if (e == i0) continue;
            if (i1 < 0 || v[e] > v[i1]) i1 = e;                  // stable second
        }
        float ew = expf(v[i1] - v[i0]);          // softmax over [v0, v1]
        float w0 = 1.f / (1.f + ew);
        float w1 = ew / (1.f + ew);

        int p0 = atomicAdd(&g_cnt[i0], 1);
        g_list[i0 * NTOK + p0] = t;  g_wgt[i0 * NTOK + p0] = w0;
        int p1 = atomicAdd(&g_cnt[i1], 1);
        g_list[i1 * NTOK + p1] = t;  g_wgt[i1 * NTOK + p1] = w1;

        if (gate_logits)
            for (int e = 0; e < NE; e++) gate_logits[(size_t)t * NE + e] = v[e];
        if (topk) { topk[t * 2] = (float)i0; topk[t * 2 + 1] = (float)i1; }
        if (counts) { atomicAdd(&counts[i0], 1.f); atomicAdd(&counts[i1], 1.f); }
    }
}

// ---------------- tf32 helpers ----------------
__device__ __forceinline__ float to_tf32(float x) {
    uint32_t r;
    asm("cvt.rna.tf32.f32 %0, %1;" : "=r"(r) : "f"(x));
    return __uint_as_float(r);
}
__device__ __forceinline__ float4 cvt4(float4 v) {
    v.x = to_tf32(v.x); v.y = to_tf32(v.y);
    v.z = to_tf32(v.z); v.w = to_tf32(v.w);
    return v;
}
__device__ __forceinline__ void mma8(float* c, const uint32_t* a, const uint32_t* b) {
    asm volatile(
        "mma.sync.aligned.m16n8k8.row.col.f32.tf32.tf32.f32 "
        "{%0,%1,%2,%3}, {%4,%5,%6,%7}, {%8,%9}, {%0,%1,%2,%3};"
        : "+f"(c[0]), "+f"(c[1]), "+f"(c[2]), "+f"(c[3])
        : "r"(a[0]), "r"(a[1]), "r"(a[2]), "r"(a[3]), "r"(b[0]), "r"(b[1]));
}

// ---------------- sparse per-expert GEMM ----------------
// MODE 1: A = gathered x rows, epilogue = gelu -> g_H
// MODE 2: A = g_H (contiguous), epilogue = weighted atomic scatter -> out
template <int KTOT, int LDB, int MODE>
__global__ void __launch_bounds__(256)
moe_gemm(const float* __restrict__ Asrc, const float* __restrict__ Bsrc,
         const float* __restrict__ bias, float* __restrict__ out) {
    constexpr int BM = 128, BN = 128, BK = 16, SA = 20, SB = 136;
    int e = blockIdx.z;
    int cnt = g_cnt[e];
    int m0 = blockIdx.y * BM;
    if (m0 >= cnt) return;
    int n0 = blockIdx.x * BN;
    int rows = cnt - m0; if (rows > BM) rows = BM;

    __shared__ float sA[2][BM][SA];
    __shared__ float sB[2][BK][SB];
    __shared__ int sTok[BM];

    int tid = threadIdx.x, lane = tid & 31, wid = tid >> 5;
    int wm = wid >> 2, wn = wid & 3;   // 2x4 warp grid, warp tile 64x32

    if (tid < BM) sTok[tid] = g_list[e * NTOK + m0 + tid];
    __syncthreads();

    const float* pA[2]; const float* pB[2];
    int ar[2], aq[2], bk_[2], bn_[2];
#pragma unroll
    for (int i = 0; i < 2; i++) {
        int lin = tid + i * 256;
        int r = lin >> 2, q = lin & 3;
        ar[i] = r; aq[i] = q;
        if (MODE == 1) pA[i] = Asrc + (size_t)sTok[r] * DD + q * 4;
        else           pA[i] = g_H + ((size_t)e * NTOK + m0 + r) * FF + q * 4;
        int bk = lin >> 5, bn = lin & 31;
        bk_[i] = bk; bn_[i] = bn;
        pB[i] = Bsrc + (size_t)e * KTOT * LDB + (size_t)bk * LDB + n0 + bn * 4;
    }

    float c[4][4][4];
#pragma unroll
    for (int a = 0; a < 4; a++)
#pragma unroll
        for (int b = 0; b < 4; b++)
#pragma unroll
            for (int r = 0; r < 4; r++) c[a][b][r] = 0.f;

    auto compute = [&](int buf) {
        int lr = lane >> 2, lc = lane & 3;
#pragma unroll
        for (int kk = 0; kk < BK; kk += 8) {
            uint32_t af[4][4], bf[4][2];
#pragma unroll
            for (int ms = 0; ms < 4; ms++) {
                int r = wm * 64 + ms * 16 + lr;
                af[ms][0] = __float_as_uint(sA[buf][r][kk + lc]);
                af[ms][1] = __float_as_uint(sA[buf][r + 8][kk + lc]);
                af[ms][2] = __float_as_uint(sA[buf][r][kk + lc + 4]);
                af[ms][3] = __float_as_uint(sA[buf][r + 8][kk + lc + 4]);
            }
#pragma unroll
            for (int ns = 0; ns < 4; ns++) {
                int cc = wn * 32 + ns * 8 + lr;
                bf[ns][0] = __float_as_uint(sB[buf][kk + lc][cc]);
                bf[ns][1] = __float_as_uint(sB[buf][kk + lc + 4][cc]);
            }
#pragma unroll
            for (int ms = 0; ms < 4; ms++)
#pragma unroll
                for (int ns = 0; ns < 4; ns++)
                    mma8(c[ms][ns], af[ms], bf[ns]);
        }
    };

    float4 ra[2], rb[2];
#pragma unroll
    for (int i = 0; i < 2; i++) {
        ra[i] = *(const float4*)pA[i];
        rb[i] = *(const float4*)pB[i];
    }
#pragma unroll
    for (int i = 0; i < 2; i++) {
        *(float4*)&sA[0][ar[i]][aq[i] * 4] = cvt4(ra[i]);
        *(float4*)&sB[0][bk_[i]][bn_[i] * 4] = cvt4(rb[i]);
    }
    __syncthreads();

    int st = 0;
    const int KIT = KTOT / BK;
    for (int kt = 1; kt < KIT; kt++) {
#pragma unroll
        for (int i = 0; i < 2; i++) {
            ra[i] = *(const float4*)(pA[i] + (size_t)kt * BK);
            rb[i] = *(const float4*)(pB[i] + (size_t)kt * BK * LDB);
        }
        compute(st);
#pragma unroll
        for (int i = 0; i < 2; i++) {
            *(float4*)&sA[st ^ 1][ar[i]][aq[i] * 4] = cvt4(ra[i]);
            *(float4*)&sB[st ^ 1][bk_[i]][bn_[i] * 4] = cvt4(rb[i]);
        }
        __syncthreads();
        st ^= 1;
    }
    compute(st);

    // -------- epilogue --------
    int lr = lane >> 2, lc = lane & 3;
#pragma unroll
    for (int ms = 0; ms < 4; ms++) {
        int rb0 = wm * 64 + ms * 16 + lr;
#pragma unroll
        for (int half = 0; half < 2; half++) {
            int r = rb0 + half * 8;
            if (r >= rows) continue;
            if (MODE == 1) {
                size_t rowbase = ((size_t)e * NTOK + m0 + r) * FF;
#pragma unroll
                for (int ns = 0; ns < 4; ns++) {
                    int col = n0 + wn * 32 + ns * 8 + lc * 2;
                    float v0 = c[ms][ns][half * 2 + 0] + bias[(size_t)e * FF + col];
                    float v1 = c[ms][ns][half * 2 + 1] + bias[(size_t)e * FF + col + 1];
                    v0 = 0.5f * v0 * (1.f + erff(v0 * 0.70710678118654752f));
                    v1 = 0.5f * v1 * (1.f + erff(v1 * 0.70710678118654752f));
                    *(float2*)&g_H[rowbase + col] = make_float2(v0, v1);
                }
            } else {
                int tok = sTok[r];
                float wgt = g_wgt[e * NTOK + m0 + r];
                size_t obase = (size_t)tok * DD;
#pragma unroll
                for (int ns = 0; ns < 4; ns++) {
                    int col = n0 + wn * 32 + ns * 8 + lc * 2;
                    float v0 = c[ms][ns][half * 2 + 0] + bias[(size_t)e * DD + col];
                    float v1 = c[ms][ns][half * 2 + 1] + bias[(size_t)e * DD + col + 1];
                    atomicAdd(&out[obase + col], wgt * v0);
                    atomicAdd(&out[obase + col + 1], wgt * v1);
                }
            }
        }
    }
}

// ---------------- launch ----------------
extern "C" void kernel_launch(void* const* d_in, const int* in_sizes, int n_in,
                              void* d_out, int out_size) {
    const float* x  = (const float*)d_in[0];
    const float* gw = (const float*)d_in[1];
    const float* gb = (const float*)d_in[2];
    const float* w1 = (const float*)d_in[3];
    const float* b1 = (const float*)d_in[4];
    const float* w2 = (const float*)d_in[5];
    const float* b2 = (const float*)d_in[6];
    float* out = (float*)d_out;

    const long long OUT0 = (long long)NTOK * DD;           // 4194304
    long long os = out_size;
    float* gl = nullptr; float* tk = nullptr; float* cn = nullptr;
    if (os >= OUT0 + (long long)NTOK * NE)
        gl = out + OUT0;
    if (os >= OUT0 + (long long)NTOK * NE + NTOK * 2)
        tk = out + OUT0 + (long long)NTOK * NE;
    if (os >= OUT0 + (long long)NTOK * NE + NTOK * 2 + NE)
        cn = out + OUT0 + (long long)NTOK * NE + NTOK * 2;

    init_kernel<<<2048, 256>>>(out, cn);
    gate_kernel<<<NTOK, 256>>>(x, gw, gb, gl, tk, cn);
    moe_gemm<DD, FF, 1><<<dim3(FF / 128, NTOK / 128, NE), 256>>>(x, w1, b1, nullptr);
    moe_gemm<FF, DD, 2><<<dim3(DD / 128, NTOK / 128, NE), 256>>>(nullptr, w2, b2, out);
}

// round 4
// speedup vs baseline: 1.6775x; 1.6775x over previous
#include <cuda_runtime.h>
#include <math.h>
#include <stdint.h>

#define NTOK 4096   // B*T
#define DD   1024   // model dim
#define NE   8      // experts
#define FF   4096   // ffn dim

// ---------------- device scratch ----------------
__device__ int   g_cnt[NE];
__device__ int   g_list[NE * NTOK];
__device__ int   g_cp[NTOK * 2];     // token -> (expert*NTOK + pos) for its 2 slots
__device__ float g_cw[NTOK * 2];     // token -> softmax weights
__device__ float g_H[(size_t)NE * NTOK * FF];
__device__ float g_Y[(size_t)NE * NTOK * DD];

// ---------------- init: zero counters only ----------------
__global__ void init_kernel(float* counts) {
    if (threadIdx.x < NE) {
        g_cnt[threadIdx.x] = 0;
        if (counts) counts[threadIdx.x] = 0.f;
    }
}

// ---------------- gating ----------------
__global__ void gate_kernel(const float* __restrict__ x,
                            const float* __restrict__ gw,
                            const float* __restrict__ gb,
                            float* gate_logits, float* topk, float* counts) {
    __shared__ float xs[DD];
    __shared__ float lg[NE];
    int t = blockIdx.x;
    const float4* xr = (const float4*)(x + (size_t)t * DD);
    for (int i = threadIdx.x; i < DD / 4; i += blockDim.x)
        ((float4*)xs)[i] = xr[i];
    __syncthreads();

    int w = threadIdx.x >> 5, lane = threadIdx.x & 31;
    float s = 0.f;
    for (int j = lane; j < DD; j += 32) s += xs[j] * gw[j * NE + w];
#pragma unroll
    for (int o = 16; o; o >>= 1) s += __shfl_xor_sync(0xffffffffu, s, o);
    if (lane == 0) lg[w] = s + gb[w];
    __syncthreads();

    if (threadIdx.x == 0) {
        float v[NE];
#pragma unroll
        for (int e = 0; e < NE; e++) v[e] = lg[e];
        int i0 = 0;
        for (int e = 1; e < NE; e++) if (v[e] > v[i0]) i0 = e;   // stable argmax
        int i1 = -1;
        for (int e = 0; e < NE; e++) {
            if (e == i0) continue;
            if (i1 < 0 || v[e] > v[i1]) i1 = e;                  // stable second
        }
        float ew = expf(v[i1] - v[i0]);
        float w0 = 1.f / (1.f + ew);
        float w1 = ew / (1.f + ew);

        int p0 = atomicAdd(&g_cnt[i0], 1);
        g_list[i0 * NTOK + p0] = t;
        int p1 = atomicAdd(&g_cnt[i1], 1);
        g_list[i1 * NTOK + p1] = t;
        g_cp[t * 2] = i0 * NTOK + p0;  g_cw[t * 2] = w0;
        g_cp[t * 2 + 1] = i1 * NTOK + p1;  g_cw[t * 2 + 1] = w1;

        if (gate_logits)
            for (int e = 0; e < NE; e++) gate_logits[(size_t)t * NE + e] = v[e];
        if (topk) { topk[t * 2] = (float)i0; topk[t * 2 + 1] = (float)i1; }
        if (counts) { atomicAdd(&counts[i0], 1.f); atomicAdd(&counts[i1], 1.f); }
    }
}

// ---------------- helpers ----------------
__device__ __forceinline__ float to_tf32(float x) {
    uint32_t r; asm("cvt.rna.tf32.f32 %0, %1;" : "=r"(r) : "f"(x));
    return __uint_as_float(r);
}
__device__ __forceinline__ float4 cvt4(float4 v) {
    v.x = to_tf32(v.x); v.y = to_tf32(v.y);
    v.z = to_tf32(v.z); v.w = to_tf32(v.w);
    return v;
}
__device__ __forceinline__ void mma8(float* c, const uint32_t* a, const uint32_t* b) {
    asm volatile(
        "mma.sync.aligned.m16n8k8.row.col.f32.tf32.tf32.f32 "
        "{%0,%1,%2,%3}, {%4,%5,%6,%7}, {%8,%9}, {%0,%1,%2,%3};"
        : "+f"(c[0]), "+f"(c[1]), "+f"(c[2]), "+f"(c[3])
        : "r"(a[0]), "r"(a[1]), "r"(a[2]), "r"(a[3]), "r"(b[0]), "r"(b[1]));
}
__device__ __forceinline__ float gelu(float v) {
    return 0.5f * v * (1.f + erff(v * 0.70710678118654752f));
}

// ---------------- sparse per-expert GEMM (mma.sync tf32) ----------------
// block 128x128, 128 threads, 2x2 warps, warp tile 64x64, BK=16 double-buffered
// MODE 1: A = gathered x rows -> gelu -> g_H
// MODE 2: A = g_H rows -> +bias -> g_Y (plain stores, no atomics)
template <int KTOT, int LDB, int MODE>
__global__ void __launch_bounds__(128, 2)
moe_gemm(const float* __restrict__ Asrc, const float* __restrict__ Bsrc,
         const float* __restrict__ bias) {
    constexpr int BM = 128, BN = 128, BK = 16, SA = 20, SB = 136;
    constexpr int KIT = KTOT / BK;
    __shared__ float sA[2][BM][SA];
    __shared__ float sB[2][BK][SB];
    __shared__ int sTok[BM];

    const int e = blockIdx.z;
    const int cnt = g_cnt[e];
    const int m0 = blockIdx.y * BM;
    if (m0 >= cnt) return;
    const int n0 = blockIdx.x * BN;
    const int rows = min(cnt - m0, BM);
    const int tid = threadIdx.x, lane = tid & 31, wid = tid >> 5;
    const int wm = wid >> 1, wn = wid & 1;

    if (tid < BM) sTok[tid] = g_list[e * NTOK + m0 + min(tid, rows - 1)];
    __syncthreads();

    const float* pA[4]; int aR[4], aQ[4];
#pragma unroll
    for (int i = 0; i < 4; i++) {
        int idx = tid + i * 128, r = idx >> 2, q = idx & 3;
        aR[i] = r; aQ[i] = q;
        size_t rb;
        if (MODE == 1) rb = (size_t)sTok[r] * DD;
        else           rb = ((size_t)e * NTOK + m0 + r) * FF;
        pA[i] = ((MODE == 1) ? Asrc : (const float*)g_H) + rb + q * 4;
    }
    const float* pB[4]; int bK[4], bN[4];
#pragma unroll
    for (int i = 0; i < 4; i++) {
        int idx = tid + i * 128, k = idx >> 5, nq = idx & 31;
        bK[i] = k; bN[i] = nq;
        pB[i] = Bsrc + (size_t)e * KTOT * LDB + (size_t)k * LDB + n0 + nq * 4;
    }

    float c[4][8][4];
#pragma unroll
    for (int a = 0; a < 4; a++)
#pragma unroll
        for (int b = 0; b < 8; b++)
#pragma unroll
            for (int r = 0; r < 4; r++) c[a][b][r] = 0.f;

    float4 ra[4], rb4[4];
    auto loadRegs = [&](int kt) {
#pragma unroll
        for (int i = 0; i < 4; i++) ra[i] = *(const float4*)(pA[i] + (size_t)kt * BK);
#pragma unroll
        for (int i = 0; i < 4; i++)
            rb4[i] = *(const float4*)(pB[i] + (size_t)kt * BK * LDB);
    };
    auto storeRegs = [&](int b) {
#pragma unroll
        for (int i = 0; i < 4; i++)
            *(float4*)&sA[b][aR[i]][aQ[i] * 4] = cvt4(ra[i]);
#pragma unroll
        for (int i = 0; i < 4; i++)
            *(float4*)&sB[b][bK[i]][bN[i] * 4] = cvt4(rb4[i]);
    };
    const int lr = lane >> 2, lc = lane & 3;
    auto compute = [&](int b) {
#pragma unroll
        for (int kk = 0; kk < BK; kk += 8) {
            uint32_t af[4][4], bf[8][2];
#pragma unroll
            for (int ms = 0; ms < 4; ms++) {
                int r = wm * 64 + ms * 16 + lr;
                af[ms][0] = __float_as_uint(sA[b][r][kk + lc]);
                af[ms][1] = __float_as_uint(sA[b][r + 8][kk + lc]);
                af[ms][2] = __float_as_uint(sA[b][r][kk + lc + 4]);
                af[ms][3] = __float_as_uint(sA[b][r + 8][kk + lc + 4]);
            }
#pragma unroll
            for (int ns = 0; ns < 8; ns++) {
                int cc = wn * 64 + ns * 8 + lr;
                bf[ns][0] = __float_as_uint(sB[b][kk + lc][cc]);
                bf[ns][1] = __float_as_uint(sB[b][kk + lc + 4][cc]);
            }
#pragma unroll
            for (int ms = 0; ms < 4; ms++)
#pragma unroll
                for (int ns = 0; ns < 8; ns++)
                    mma8(c[ms][ns], af[ms], bf[ns]);
        }
    };

    loadRegs(0);
    storeRegs(0);
    __syncthreads();
    for (int kt = 1; kt < KIT; kt++) {
        loadRegs(kt);
        compute((kt - 1) & 1);
        storeRegs(kt & 1);
        __syncthreads();
    }
    compute((KIT - 1) & 1);

    // -------- epilogue: plain stores --------
    constexpr int ND = (MODE == 1) ? FF : DD;
#pragma unroll
    for (int ms = 0; ms < 4; ms++) {
#pragma unroll
        for (int half = 0; half < 2; half++) {
            int r = wm * 64 + ms * 16 + lr + half * 8;
            if (r >= rows) continue;
            size_t rowb = ((size_t)e * NTOK + m0 + r) * ND;
#pragma unroll
            for (int ns = 0; ns < 8; ns++) {
                int col = n0 + wn * 64 + ns * 8 + lc * 2;
                float2 bv = *(const float2*)&bias[(size_t)e * ND + col];
                float v0 = c[ms][ns][half * 2 + 0] + bv.x;
                float v1 = c[ms][ns][half * 2 + 1] + bv.y;
                if (MODE == 1) {
                    v0 = gelu(v0); v1 = gelu(v1);
                    *(float2*)&g_H[rowb + col] = make_float2(v0, v1);
                } else {
                    *(float2*)&g_Y[rowb + col] = make_float2(v0, v1);
                }
            }
        }
    }
}

// ---------------- combine: out[t] = w0*Y[p0] + w1*Y[p1] ----------------
__global__ void combine_kernel(float* __restrict__ out) {
    int t = blockIdx.x;
    int i = threadIdx.x;                 // 256 threads * float4 = 1024
    int p0 = g_cp[t * 2], p1 = g_cp[t * 2 + 1];
    float w0 = g_cw[t * 2], w1 = g_cw[t * 2 + 1];
    const float4* y0 = (const float4*)(g_Y + (size_t)p0 * DD);
    const float4* y1 = (const float4*)(g_Y + (size_t)p1 * DD);
    float4 a = y0[i], b = y1[i], r;
    r.x = w0 * a.x + w1 * b.x;
    r.y = w0 * a.y + w1 * b.y;
    r.z = w0 * a.z + w1 * b.z;
    r.w = w0 * a.w + w1 * b.w;
    ((float4*)(out + (size_t)t * DD))[i] = r;
}

// ---------------- launch ----------------
extern "C" void kernel_launch(void* const* d_in, const int* in_sizes, int n_in,
                              void* d_out, int out_size) {
    const float* x  = (const float*)d_in[0];
    const float* gw = (const float*)d_in[1];
    const float* gb = (const float*)d_in[2];
    const float* w1 = (const float*)d_in[3];
    const float* b1 = (const float*)d_in[4];
    const float* w2 = (const float*)d_in[5];
    const float* b2 = (const float*)d_in[6];
    float* out = (float*)d_out;

    const long long OUT0 = (long long)NTOK * DD;
    long long os = out_size;
    float* gl = nullptr; float* tk = nullptr; float* cn = nullptr;
    if (os >= OUT0 + (long long)NTOK * NE)
        gl = out + OUT0;
    if (os >= OUT0 + (long long)NTOK * NE + NTOK * 2)
        tk = out + OUT0 + (long long)NTOK * NE;
    if (os >= OUT0 + (long long)NTOK * NE + NTOK * 2 + NE)
        cn = out + OUT0 + (long long)NTOK * NE + NTOK * 2;

    init_kernel<<<1, 32>>>(cn);
    gate_kernel<<<NTOK, 256>>>(x, gw, gb, gl, tk, cn);
    moe_gemm<DD, FF, 1><<<dim3(FF / 128, NTOK / 128, NE), 128>>>(x, w1, b1);
    moe_gemm<FF, DD, 2><<<dim3(DD / 128, NTOK / 128, NE), 128>>>(nullptr, w2, b2);
    combine_kernel<<<NTOK, 256>>>(out);
}

// round 5
// speedup vs baseline: 2.8478x; 1.6976x over previous
#include <cuda_runtime.h>
#include <cuda_fp16.h>
#include <math.h>
#include <stdint.h>

#define NTOK 4096   // B*T
#define DD   1024   // model dim
#define NE   8      // experts
#define FF   4096   // ffn dim

// ---------------- device scratch ----------------
__device__ int    g_cnt[NE];
__device__ int    g_list[NE * NTOK];
__device__ int    g_cp[NTOK * 2];
__device__ float  g_cw[NTOK * 2];
__device__ __half g_H[(size_t)NE * NTOK * FF];   // fp16 hidden
__device__ float  g_Y[(size_t)NE * NTOK * DD];

// ---------------- init ----------------
__global__ void init_kernel(float* counts) {
    if (threadIdx.x < NE) {
        g_cnt[threadIdx.x] = 0;
        if (counts) counts[threadIdx.x] = 0.f;
    }
}

// ---------------- gating ----------------
__global__ void gate_kernel(const float* __restrict__ x,
                            const float* __restrict__ gw,
                            const float* __restrict__ gb,
                            float* gate_logits, float* topk, float* counts) {
    __shared__ float xs[DD];
    __shared__ float lg[NE];
    int t = blockIdx.x;
    const float4* xr = (const float4*)(x + (size_t)t * DD);
    for (int i = threadIdx.x; i < DD / 4; i += blockDim.x)
        ((float4*)xs)[i] = xr[i];
    __syncthreads();

    int w = threadIdx.x >> 5, lane = threadIdx.x & 31;
    float s = 0.f;
    for (int j = lane; j < DD; j += 32) s += xs[j] * gw[j * NE + w];
#pragma unroll
    for (int o = 16; o; o >>= 1) s += __shfl_xor_sync(0xffffffffu, s, o);
    if (lane == 0) lg[w] = s + gb[w];
    __syncthreads();

    if (threadIdx.x == 0) {
        float v[NE];
#pragma unroll
        for (int e = 0; e < NE; e++) v[e] = lg[e];
        int i0 = 0;
        for (int e = 1; e < NE; e++) if (v[e] > v[i0]) i0 = e;
        int i1 = -1;
        for (int e = 0; e < NE; e++) {
            if (e == i0) continue;
            if (i1 < 0 || v[e] > v[i1]) i1 = e;
        }
        float ew = expf(v[i1] - v[i0]);
        float w0 = 1.f / (1.f + ew);
        float w1 = ew / (1.f + ew);

        int p0 = atomicAdd(&g_cnt[i0], 1);
        g_list[i0 * NTOK + p0] = t;
        int p1 = atomicAdd(&g_cnt[i1], 1);
        g_list[i1 * NTOK + p1] = t;
        g_cp[t * 2] = i0 * NTOK + p0;  g_cw[t * 2] = w0;
        g_cp[t * 2 + 1] = i1 * NTOK + p1;  g_cw[t * 2 + 1] = w1;

        if (gate_logits)
            for (int e = 0; e < NE; e++) gate_logits[(size_t)t * NE + e] = v[e];
        if (topk) { topk[t * 2] = (float)i0; topk[t * 2 + 1] = (float)i1; }
        if (counts) { atomicAdd(&counts[i0], 1.f); atomicAdd(&counts[i1], 1.f); }
    }
}

// ---------------- helpers ----------------
__device__ __forceinline__ void mma16(float* c, const uint32_t* a, const uint32_t* b) {
    asm volatile(
        "mma.sync.aligned.m16n8k16.row.col.f32.f16.f16.f32 "
        "{%0,%1,%2,%3}, {%4,%5,%6,%7}, {%8,%9}, {%0,%1,%2,%3};"
        : "+f"(c[0]), "+f"(c[1]), "+f"(c[2]), "+f"(c[3])
        : "r"(a[0]), "r"(a[1]), "r"(a[2]), "r"(a[3]), "r"(b[0]), "r"(b[1]));
}
__device__ __forceinline__ float gelu(float v) {
    return 0.5f * v * (1.f + erff(v * 0.70710678118654752f));
}
__device__ __forceinline__ uint32_t h2bits(__half2 h) {
    return *(uint32_t*)&h;
}

// ---------------- sparse per-expert GEMM (mma.sync fp16, fp32 accum) ----------------
// block 128x128, 128 threads, 2x2 warps (warp tile 64x64), BK=32 double-buffered
// MODE 1: A = gathered x rows (fp32->fp16) -> gelu -> g_H (fp16)
// MODE 2: A = g_H rows (fp16) -> +bias -> g_Y (fp32)
template <int KTOT, int LDB, int MODE>
__global__ void __launch_bounds__(128, 2)
moe_gemm(const float* __restrict__ Asrc, const float* __restrict__ Bsrc,
         const float* __restrict__ bias) {
    constexpr int BM = 128, BN = 128, BK = 32;
    constexpr int SAH = 40;     // halfs per A row (32 + 8 pad) -> 80B pitch
    constexpr int SBW = 136;    // half2 per B k-pair row (128 + 8 pad) -> 544B pitch
    constexpr int KIT = KTOT / BK;
    __shared__ __half  sA[2][BM][SAH];
    __shared__ __half2 sB[2][BK / 2][SBW];
    __shared__ int sTok[BM];

    const int e = blockIdx.z;
    const int cnt = g_cnt[e];
    const int m0 = blockIdx.y * BM;
    if (m0 >= cnt) return;
    const int n0 = blockIdx.x * BN;
    const int rows = min(cnt - m0, BM);
    const int tid = threadIdx.x, lane = tid & 31, wid = tid >> 5;
    const int wm = wid >> 1, wn = wid & 1;

    if (tid < BM) sTok[tid] = g_list[e * NTOK + m0 + min(tid, rows - 1)];
    __syncthreads();

    // ---- A pointers ----
    const float*  pA1[8]; int aR1[8], aQ1[8];     // MODE 1: fp32 x rows
    const __half* pA2[4]; int aR2[4], aQ2[4];     // MODE 2: fp16 g_H rows
    if (MODE == 1) {
#pragma unroll
        for (int i = 0; i < 8; i++) {
            int idx = tid + i * 128, r = idx >> 3, q = idx & 7;
            aR1[i] = r; aQ1[i] = q;
            pA1[i] = Asrc + (size_t)sTok[r] * DD + q * 4;
        }
    } else {
#pragma unroll
        for (int i = 0; i < 4; i++) {
            int idx = tid + i * 128, r = idx >> 2, q = idx & 3;
            aR2[i] = r; aQ2[i] = q;
            pA2[i] = g_H + ((size_t)e * NTOK + m0 + r) * FF + q * 8;
        }
    }
    // ---- B pointers: thread handles (kpair, n-quad) ----
    const float* pB[4]; int bKp[4], bNq[4];
#pragma unroll
    for (int i = 0; i < 4; i++) {
        int idx = tid + i * 128, kp = idx >> 5, nq = idx & 31;
        bKp[i] = kp; bNq[i] = nq;
        pB[i] = Bsrc + (size_t)e * KTOT * LDB + (size_t)(2 * kp) * LDB + n0 + nq * 4;
    }

    float c[4][8][4];
#pragma unroll
    for (int a = 0; a < 4; a++)
#pragma unroll
        for (int b = 0; b < 8; b++)
#pragma unroll
            for (int r = 0; r < 4; r++) c[a][b][r] = 0.f;

    float4 ra[8]; uint4 ua[4];
    float4 rb0[4], rb1[4];
    auto loadRegs = [&](int kt) {
        if (MODE == 1) {
#pragma unroll
            for (int i = 0; i < 8; i++) ra[i] = *(const float4*)(pA1[i] + (size_t)kt * BK);
        } else {
#pragma unroll
            for (int i = 0; i < 4; i++) ua[i] = *(const uint4*)(pA2[i] + (size_t)kt * BK);
        }
#pragma unroll
        for (int i = 0; i < 4; i++) {
            rb0[i] = *(const float4*)(pB[i] + (size_t)kt * BK * LDB);
            rb1[i] = *(const float4*)(pB[i] + (size_t)kt * BK * LDB + LDB);
        }
    };
    auto storeRegs = [&](int b) {
        if (MODE == 1) {
#pragma unroll
            for (int i = 0; i < 8; i++) {
                __half2 h0 = __halves2half2(__float2half_rn(ra[i].x), __float2half_rn(ra[i].y));
                __half2 h1 = __halves2half2(__float2half_rn(ra[i].z), __float2half_rn(ra[i].w));
                uint2 u; u.x = h2bits(h0); u.y = h2bits(h1);
                *(uint2*)&sA[b][aR1[i]][aQ1[i] * 4] = u;
            }
        } else {
#pragma unroll
            for (int i = 0; i < 4; i++)
                *(uint4*)&sA[b][aR2[i]][aQ2[i] * 8] = ua[i];
        }
#pragma unroll
        for (int i = 0; i < 4; i++) {
            const float* f0 = (const float*)&rb0[i];
            const float* f1 = (const float*)&rb1[i];
            uint4 u;
            u.x = h2bits(__halves2half2(__float2half_rn(f0[0]), __float2half_rn(f1[0])));
            u.y = h2bits(__halves2half2(__float2half_rn(f0[1]), __float2half_rn(f1[1])));
            u.z = h2bits(__halves2half2(__float2half_rn(f0[2]), __float2half_rn(f1[2])));
            u.w = h2bits(__halves2half2(__float2half_rn(f0[3]), __float2half_rn(f1[3])));
            *(uint4*)&sB[b][bKp[i]][bNq[i] * 4] = u;
        }
    };
    const int lr = lane >> 2, lc = lane & 3;
    auto compute = [&](int b) {
#pragma unroll
        for (int s = 0; s < 2; s++) {          // two k16 slabs per BK=32
            uint32_t af[4][4], bf[8][2];
#pragma unroll
            for (int ms = 0; ms < 4; ms++) {
                int r = wm * 64 + ms * 16 + lr;
                af[ms][0] = *(const uint32_t*)&sA[b][r][s * 16 + 2 * lc];
                af[ms][1] = *(const uint32_t*)&sA[b][r + 8][s * 16 + 2 * lc];
                af[ms][2] = *(const uint32_t*)&sA[b][r][s * 16 + 2 * lc + 8];
                af[ms][3] = *(const uint32_t*)&sA[b][r + 8][s * 16 + 2 * lc + 8];
            }
#pragma unroll
            for (int ns = 0; ns < 8; ns++) {
                int cc = wn * 64 + ns * 8 + lr;
                bf[ns][0] = *(const uint32_t*)&sB[b][s * 8 + lc][cc];
                bf[ns][1] = *(const uint32_t*)&sB[b][s * 8 + lc + 4][cc];
            }
#pragma unroll
            for (int ms = 0; ms < 4; ms++)
#pragma unroll
                for (int ns = 0; ns < 8; ns++)
                    mma16(c[ms][ns], af[ms], bf[ns]);
        }
    };

    loadRegs(0);
    storeRegs(0);
    __syncthreads();
    for (int kt = 1; kt < KIT; kt++) {
        loadRegs(kt);
        compute((kt - 1) & 1);
        storeRegs(kt & 1);
        __syncthreads();
    }
    compute((KIT - 1) & 1);

    // -------- epilogue --------
    constexpr int ND = (MODE == 1) ? FF : DD;
#pragma unroll
    for (int ms = 0; ms < 4; ms++) {
#pragma unroll
        for (int half = 0; half < 2; half++) {
            int r = wm * 64 + ms * 16 + lr + half * 8;
            if (r >= rows) continue;
            size_t rowb = ((size_t)e * NTOK + m0 + r) * ND;
#pragma unroll
            for (int ns = 0; ns < 8; ns++) {
                int col = n0 + wn * 64 + ns * 8 + lc * 2;
                float2 bv = *(const float2*)&bias[(size_t)e * ND + col];
                float v0 = c[ms][ns][half * 2 + 0] + bv.x;
                float v1 = c[ms][ns][half * 2 + 1] + bv.y;
                if (MODE == 1) {
                    v0 = gelu(v0); v1 = gelu(v1);
                    *(__half2*)&g_H[rowb + col] =
                        __halves2half2(__float2half_rn(v0), __float2half_rn(v1));
                } else {
                    *(float2*)&g_Y[rowb + col] = make_float2(v0, v1);
                }
            }
        }
    }
}

// ---------------- combine: out[t] = w0*Y[p0] + w1*Y[p1] ----------------
__global__ void combine_kernel(float* __restrict__ out) {
    int t = blockIdx.x;
    int i = threadIdx.x;
    int p0 = g_cp[t * 2], p1 = g_cp[t * 2 + 1];
    float w0 = g_cw[t * 2], w1 = g_cw[t * 2 + 1];
    const float4* y0 = (const float4*)(g_Y + (size_t)p0 * DD);
    const float4* y1 = (const float4*)(g_Y + (size_t)p1 * DD);
    float4 a = y0[i], b = y1[i], r;
    r.x = w0 * a.x + w1 * b.x;
    r.y = w0 * a.y + w1 * b.y;
    r.z = w0 * a.z + w1 * b.z;
    r.w = w0 * a.w + w1 * b.w;
    ((float4*)(out + (size_t)t * DD))[i] = r;
}

// ---------------- launch ----------------
extern "C" void kernel_launch(void* const* d_in, const int* in_sizes, int n_in,
                              void* d_out, int out_size) {
    const float* x  = (const float*)d_in[0];
    const float* gw = (const float*)d_in[1];
    const float* gb = (const float*)d_in[2];
    const float* w1 = (const float*)d_in[3];
    const float* b1 = (const float*)d_in[4];
    const float* w2 = (const float*)d_in[5];
    const float* b2 = (const float*)d_in[6];
    float* out = (float*)d_out;

    const long long OUT0 = (long long)NTOK * DD;
    long long os = out_size;
    float* gl = nullptr; float* tk = nullptr; float* cn = nullptr;
    if (os >= OUT0 + (long long)NTOK * NE)
        gl = out + OUT0;
    if (os >= OUT0 + (long long)NTOK * NE + NTOK * 2)
        tk = out + OUT0 + (long long)NTOK * NE;
    if (os >= OUT0 + (long long)NTOK * NE + NTOK * 2 + NE)
        cn = out + OUT0 + (long long)NTOK * NE + NTOK * 2;

    init_kernel<<<1, 32>>>(cn);
    gate_kernel<<<NTOK, 256>>>(x, gw, gb, gl, tk, cn);
    moe_gemm<DD, FF, 1><<<dim3(FF / 128, NTOK / 128, NE), 128>>>(x, w1, b1);
    moe_gemm<FF, DD, 2><<<dim3(DD / 128, NTOK / 128, NE), 128>>>(nullptr, w2, b2);
    combine_kernel<<<NTOK, 256>>>(out);
}

// round 6
// speedup vs baseline: 3.2624x; 1.1456x over previous
#include <cuda_runtime.h>
#include <cuda_fp16.h>
#include <math.h>
#include <stdint.h>

#define NTOK 4096   // B*T
#define DD   1024   // model dim
#define NE   8      // experts
#define FF   4096   // ffn dim

// ---------------- device scratch ----------------
__device__ int    g_cnt[NE];
__device__ int    g_list[NE * NTOK];
__device__ int    g_cp[NTOK * 2];
__device__ float  g_cw[NTOK * 2];
__device__ __half g_Xh[(size_t)NTOK * DD];
__device__ __half g_W1h[(size_t)NE * DD * FF];
__device__ __half g_W2h[(size_t)NE * FF * DD];
__device__ __half g_H[(size_t)NE * NTOK * FF];
__device__ float  g_Y[(size_t)NE * NTOK * DD];

// ---------------- init ----------------
__global__ void init_kernel(float* counts) {
    if (threadIdx.x < NE) {
        g_cnt[threadIdx.x] = 0;
        if (counts) counts[threadIdx.x] = 0.f;
    }
}

// ---------------- fp32 -> fp16 conversion ----------------
__global__ void f2h_kernel(const float* __restrict__ src, __half* __restrict__ dst,
                           int n4) {
    int stride = gridDim.x * blockDim.x;
    for (int i = blockIdx.x * blockDim.x + threadIdx.x; i < n4; i += stride) {
        float4 v = ((const float4*)src)[i];
        __half2 h0 = __halves2half2(__float2half_rn(v.x), __float2half_rn(v.y));
        __half2 h1 = __halves2half2(__float2half_rn(v.z), __float2half_rn(v.w));
        uint2 u;
        u.x = *(uint32_t*)&h0;
        u.y = *(uint32_t*)&h1;
        ((uint2*)dst)[i] = u;
    }
}

// ---------------- gating (fp32, exact top-k semantics) ----------------
__global__ void gate_kernel(const float* __restrict__ x,
                            const float* __restrict__ gw,
                            const float* __restrict__ gb,
                            float* gate_logits, float* topk, float* counts) {
    __shared__ float xs[DD];
    __shared__ float lg[NE];
    int t = blockIdx.x;
    const float4* xr = (const float4*)(x + (size_t)t * DD);
    for (int i = threadIdx.x; i < DD / 4; i += blockDim.x)
        ((float4*)xs)[i] = xr[i];
    __syncthreads();

    int w = threadIdx.x >> 5, lane = threadIdx.x & 31;
    float s = 0.f;
    for (int j = lane; j < DD; j += 32) s += xs[j] * gw[j * NE + w];
#pragma unroll
    for (int o = 16; o; o >>= 1) s += __shfl_xor_sync(0xffffffffu, s, o);
    if (lane == 0) lg[w] = s + gb[w];
    __syncthreads();

    if (threadIdx.x == 0) {
        float v[NE];
#pragma unroll
        for (int e = 0; e < NE; e++) v[e] = lg[e];
        int i0 = 0;
        for (int e = 1; e < NE; e++) if (v[e] > v[i0]) i0 = e;
        int i1 = -1;
        for (int e = 0; e < NE; e++) {
            if (e == i0) continue;
            if (i1 < 0 || v[e] > v[i1]) i1 = e;
        }
        float ew = expf(v[i1] - v[i0]);
        float w0 = 1.f / (1.f + ew);
        float w1 = ew / (1.f + ew);

        int p0 = atomicAdd(&g_cnt[i0], 1);
        g_list[i0 * NTOK + p0] = t;
        int p1 = atomicAdd(&g_cnt[i1], 1);
        g_list[i1 * NTOK + p1] = t;
        g_cp[t * 2] = i0 * NTOK + p0;  g_cw[t * 2] = w0;
        g_cp[t * 2 + 1] = i1 * NTOK + p1;  g_cw[t * 2 + 1] = w1;

        if (gate_logits)
            for (int e = 0; e < NE; e++) gate_logits[(size_t)t * NE + e] = v[e];
        if (topk) { topk[t * 2] = (float)i0; topk[t * 2 + 1] = (float)i1; }
        if (counts) { atomicAdd(&counts[i0], 1.f); atomicAdd(&counts[i1], 1.f); }
    }
}

// ---------------- helpers ----------------
__device__ __forceinline__ uint32_t smem_u32(const void* p) {
    uint32_t a;
    asm("{ .reg .u64 t; cvta.to.shared.u64 t, %1; cvt.u32.u64 %0, t; }"
        : "=r"(a) : "l"(p));
    return a;
}
__device__ __forceinline__ void mma16(float* c, const uint32_t* a, const uint32_t* b) {
    asm volatile(
        "mma.sync.aligned.m16n8k16.row.col.f32.f16.f16.f32 "
        "{%0,%1,%2,%3}, {%4,%5,%6,%7}, {%8,%9}, {%0,%1,%2,%3};"
        : "+f"(c[0]), "+f"(c[1]), "+f"(c[2]), "+f"(c[3])
        : "r"(a[0]), "r"(a[1]), "r"(a[2]), "r"(a[3]), "r"(b[0]), "r"(b[1]));
}
__device__ __forceinline__ float gelu(float v) {
    return 0.5f * v * (1.f + erff(v * 0.70710678118654752f));
}
#define CP16(dst, src) \
    asm volatile("cp.async.cg.shared.global [%0], [%1], 16;" :: "r"(dst), "l"(src))
#define CP_COMMIT() asm volatile("cp.async.commit_group;" ::: "memory")
#define CP_WAIT2() asm volatile("cp.async.wait_group 2;" ::: "memory")

// ---------------- fp16 sparse per-expert GEMM, cp.async + ldmatrix ----------------
// block 128x128, 128 threads, 2x2 warps (64x64 warp tile), BK=32, 4-stage cp.async
// MODE 1: A = gathered g_Xh rows -> gelu -> g_H (fp16)
// MODE 2: A = g_H rows -> +bias -> g_Y (fp32)
template <int KTOT, int LDB, int MODE>
__global__ void __launch_bounds__(128, 2)
moe_gemm(const __half* __restrict__ Bh, const float* __restrict__ bias) {
    constexpr int BK = 32;
    constexpr int KIT = KTOT / BK;
    // smem: per-stage A 128 rows x 80B = 10240B; B 32 k-rows x 272B = 8704B
    constexpr int SA_ST = 10240, SB_ST = 8704;
    constexpr int OFF_B = 4 * SA_ST;            // 40960
    constexpr int OFF_TOK = OFF_B + 4 * SB_ST;  // 75776
    extern __shared__ __align__(16) char smem[];
    const uint32_t sbase = smem_u32(smem);

    const int e = blockIdx.z;
    const int cnt = g_cnt[e];
    const int m0 = blockIdx.y * 128;
    if (m0 >= cnt) return;
    const int n0 = blockIdx.x * 128;
    const int rows = min(cnt - m0, 128);
    const int tid = threadIdx.x, lane = tid & 31, wid = tid >> 5;
    const int wm = wid >> 1, wn = wid & 1;

    int* sTok = (int*)(smem + OFF_TOK);
    if (MODE == 1) {
        if (tid < 128) sTok[tid] = g_list[e * NTOK + m0 + min(tid, rows - 1)];
        __syncthreads();
    }

    // ---- gmem pointers for cp.async fills ----
    const __half* pA[4]; uint32_t aOfs[4];     // A: row r (idx>>2), chunk c (idx&3)
#pragma unroll
    for (int i = 0; i < 4; i++) {
        int idx = tid + i * 128, r = idx >> 2, c = idx & 3;
        size_t rb;
        if (MODE == 1) rb = (size_t)sTok[r] * DD;
        else           rb = ((size_t)e * NTOK + m0 + r) * FF;
        pA[i] = ((MODE == 1) ? g_Xh : g_H) + rb + c * 8;
        aOfs[i] = (uint32_t)(r * 80 + c * 16);
    }
    const __half* pB[4]; uint32_t bOfs[4];     // B: k-row (idx>>4), chunk (idx&15)
#pragma unroll
    for (int i = 0; i < 4; i++) {
        int idx = tid + i * 128, k = idx >> 4, c = idx & 15;
        pB[i] = Bh + (size_t)e * KTOT * LDB + (size_t)k * LDB + n0 + c * 8;
        bOfs[i] = (uint32_t)(k * 272 + c * 16);
    }

    // ---- fragment smem offsets (ldmatrix) ----
    uint32_t aFrag[4];
#pragma unroll
    for (int ms = 0; ms < 4; ms++) {
        int row = wm * 64 + ms * 16 + (lane & 7) + ((lane >> 3) & 1) * 8;
        aFrag[ms] = (uint32_t)(row * 80 + ((lane >> 4) & 1) * 16);
    }
    uint32_t bFrag[4];
#pragma unroll
    for (int p = 0; p < 4; p++) {
        int k = (lane & 7) + ((lane >> 3) & 1) * 8;
        int n = wn * 64 + p * 16 + ((lane >> 4) & 1) * 8;
        bFrag[p] = (uint32_t)(k * 272 + n * 2);
    }

    float c[4][8][4];
#pragma unroll
    for (int a = 0; a < 4; a++)
#pragma unroll
        for (int b = 0; b < 8; b++)
#pragma unroll
            for (int r = 0; r < 4; r++) c[a][b][r] = 0.f;

    auto fill = [&](int kt) {
        int st = kt & 3;
        uint32_t sa = sbase + st * SA_ST;
        uint32_t sb = sbase + OFF_B + st * SB_ST;
#pragma unroll
        for (int i = 0; i < 4; i++)
            CP16(sa + aOfs[i], pA[i] + (size_t)kt * BK);
#pragma unroll
        for (int i = 0; i < 4; i++)
            CP16(sb + bOfs[i], pB[i] + (size_t)kt * BK * LDB);
    };
    auto compute = [&](int kt) {
        int st = kt & 3;
        uint32_t sa = sbase + st * SA_ST;
        uint32_t sb = sbase + OFF_B + st * SB_ST;
#pragma unroll
        for (int s = 0; s < 2; s++) {
            uint32_t af[4][4], bf[8][2];
#pragma unroll
            for (int ms = 0; ms < 4; ms++) {
                uint32_t addr = sa + aFrag[ms] + s * 32;
                asm volatile(
                    "ldmatrix.sync.aligned.m8n8.x4.shared.b16 {%0,%1,%2,%3}, [%4];"
                    : "=r"(af[ms][0]), "=r"(af[ms][1]),
                      "=r"(af[ms][2]), "=r"(af[ms][3]) : "r"(addr));
            }
#pragma unroll
            for (int p = 0; p < 4; p++) {
                uint32_t addr = sb + bFrag[p] + s * (16 * 272);
                asm volatile(
                    "ldmatrix.sync.aligned.m8n8.x4.trans.shared.b16 {%0,%1,%2,%3}, [%4];"
                    : "=r"(bf[2 * p][0]), "=r"(bf[2 * p][1]),
                      "=r"(bf[2 * p + 1][0]), "=r"(bf[2 * p + 1][1]) : "r"(addr));
            }
#pragma unroll
            for (int ms = 0; ms < 4; ms++)
#pragma unroll
                for (int ns = 0; ns < 8; ns++)
                    mma16(c[ms][ns], af[ms], bf[ns]);
        }
    };

    // ---- 4-stage pipeline ----
    fill(0); CP_COMMIT();
    fill(1); CP_COMMIT();
    fill(2); CP_COMMIT();
    for (int kt = 0; kt < KIT; kt++) {
        CP_WAIT2();
        __syncthreads();
        if (kt + 3 < KIT) fill(kt + 3);
        CP_COMMIT();
        compute(kt);
    }

    // ---- epilogue ----
    constexpr int ND = (MODE == 1) ? FF : DD;
    const int lr = lane >> 2, lc = lane & 3;
#pragma unroll
    for (int ms = 0; ms < 4; ms++) {
#pragma unroll
        for (int half = 0; half < 2; half++) {
            int r = wm * 64 + ms * 16 + lr + half * 8;
            if (r >= rows) continue;
            size_t rowb = ((size_t)e * NTOK + m0 + r) * ND;
#pragma unroll
            for (int ns = 0; ns < 8; ns++) {
                int col = n0 + wn * 64 + ns * 8 + lc * 2;
                float2 bv = *(const float2*)&bias[(size_t)e * ND + col];
                float v0 = c[ms][ns][half * 2 + 0] + bv.x;
                float v1 = c[ms][ns][half * 2 + 1] + bv.y;
                if (MODE == 1) {
                    v0 = gelu(v0); v1 = gelu(v1);
                    *(__half2*)&g_H[rowb + col] =
                        __halves2half2(__float2half_rn(v0), __float2half_rn(v1));
                } else {
                    *(float2*)&g_Y[rowb + col] = make_float2(v0, v1);
                }
            }
        }
    }
}

// ---------------- combine: out[t] = w0*Y[p0] + w1*Y[p1] ----------------
__global__ void combine_kernel(float* __restrict__ out) {
    int t = blockIdx.x;
    int i = threadIdx.x;
    int p0 = g_cp[t * 2], p1 = g_cp[t * 2 + 1];
    float w0 = g_cw[t * 2], w1 = g_cw[t * 2 + 1];
    const float4* y0 = (const float4*)(g_Y + (size_t)p0 * DD);
    const float4* y1 = (const float4*)(g_Y + (size_t)p1 * DD);
    float4 a = y0[i], b = y1[i], r;
    r.x = w0 * a.x + w1 * b.x;
    r.y = w0 * a.y + w1 * b.y;
    r.z = w0 * a.z + w1 * b.z;
    r.w = w0 * a.w + w1 * b.w;
    ((float4*)(out + (size_t)t * DD))[i] = r;
}

// ---------------- launch ----------------
extern "C" void kernel_launch(void* const* d_in, const int* in_sizes, int n_in,
                              void* d_out, int out_size) {
    const float* x  = (const float*)d_in[0];
    const float* gw = (const float*)d_in[1];
    const float* gb = (const float*)d_in[2];
    const float* w1 = (const float*)d_in[3];
    const float* b1 = (const float*)d_in[4];
    const float* w2 = (const float*)d_in[5];
    const float* b2 = (const float*)d_in[6];
    float* out = (float*)d_out;

    const long long OUT0 = (long long)NTOK * DD;
    long long os = out_size;
    float* gl = nullptr; float* tk = nullptr; float* cn = nullptr;
    if (os >= OUT0 + (long long)NTOK * NE)
        gl = out + OUT0;
    if (os >= OUT0 + (long long)NTOK * NE + NTOK * 2)
        tk = out + OUT0 + (long long)NTOK * NE;
    if (os >= OUT0 + (long long)NTOK * NE + NTOK * 2 + NE)
        cn = out + OUT0 + (long long)NTOK * NE + NTOK * 2;

    static __half* xh = nullptr; static __half* w1h = nullptr; static __half* w2h = nullptr;
    if (!xh) {
        cudaGetSymbolAddress((void**)&xh, g_Xh);
        cudaGetSymbolAddress((void**)&w1h, g_W1h);
        cudaGetSymbolAddress((void**)&w2h, g_W2h);
    }

    const int SMEM = 76288;
    static bool attr_set = false;
    if (!attr_set) {
        cudaFuncSetAttribute(moe_gemm<DD, FF, 1>,
                             cudaFuncAttributeMaxDynamicSharedMemorySize, SMEM);
        cudaFuncSetAttribute(moe_gemm<FF, DD, 2>,
                             cudaFuncAttributeMaxDynamicSharedMemorySize, SMEM);
        attr_set = true;
    }

    init_kernel<<<1, 32>>>(cn);
    gate_kernel<<<NTOK, 256>>>(x, gw, gb, gl, tk, cn);
    f2h_kernel<<<2048, 256>>>(x, xh, NTOK * DD / 4);
    f2h_kernel<<<8192, 256>>>(w1, w1h, NE * DD * FF / 4);
    f2h_kernel<<<8192, 256>>>(w2, w2h, NE * FF * DD / 4);
    moe_gemm<DD, FF, 1><<<dim3(FF / 128, NTOK / 128, NE), 128, SMEM>>>(w1h, b1);
    moe_gemm<FF, DD, 2><<<dim3(DD / 128, NTOK / 128, NE), 128, SMEM>>>(w2h, b2);
    combine_kernel<<<NTOK, 256>>>(out);
}